// round 8
// baseline (speedup 1.0000x reference)
#include <cuda_runtime.h>
#include <cuda_bf16.h>

#define MAX_ATOMS 8000
#define MAX_PAIRS 80000
#define NF 32
#define NDIST 16
#define FWCOLS (NDIST * NF)       // 512
#define BIGN (FWCOLS + NF)        // 544
#define GN_EPS 1e-5f
#define HARD_CUTOFF 6.5f
#define CUT_K 0.24166097335306083f   // 0.5*pi/6.5

// Scratch (layout: fw[j][o][d], o=out channel, d=dist index)
__device__ float d_fw[MAX_ATOMS * FWCOLS];
__device__ float d_sens[MAX_PAIRS * NDIST];
__device__ int   d_start[MAX_ATOMS + 1];

// ---------------------------------------------------------------------------
// K0: sensitivities for all (pair, dist) + segment-start table (pf is sorted)
// ---------------------------------------------------------------------------
__global__ __launch_bounds__(256) void k0_prep(
    const float* __restrict__ dist,
    const float* __restrict__ mu,
    const float* __restrict__ sigma,
    const int*   __restrict__ pf,
    int n_pairs, int n_atoms)
{
    int idx = blockIdx.x * blockDim.x + threadIdx.x;
    if (idx < n_pairs * NDIST) {
        int p = idx >> 4, dd = idx & 15;
        float dv = dist[p];
        float t = (__fdividef(1.0f, dv) - mu[dd]) * __fdividef(1.0f, sigma[dd]);
        float cut = 0.0f;
        if (dv < HARD_CUTOFF) {
            float cc = __cosf(CUT_K * dv);
            cut = cc * cc;
        }
        d_sens[idx] = __expf(-0.5f * t * t) * cut;
    }
    if (idx < n_pairs) {
        int a = pf[idx];
        int prev = (idx == 0) ? -1 : pf[idx - 1];
        for (int x = prev + 1; x <= a; x++) d_start[x] = idx;
        if (idx == n_pairs - 1) {
            for (int x = a + 1; x <= n_atoms; x++) d_start[x] = n_pairs;
        }
    }
}

// ---------------------------------------------------------------------------
// K1: fused GEMM  C(N x 544) = feat(N x 32) @ Wbig(32 x 544)
//   cols [0,512): fw with layout col = o*16 + d
//   cols [512,544): self_part -> d_out (+bias)
// ---------------------------------------------------------------------------
__global__ __launch_bounds__(256) void k1_gemm(
    const float* __restrict__ feat,
    const float* __restrict__ intw,    // (16,32,32)
    const float* __restrict__ selfw,   // (32,32)
    const float* __restrict__ selfb,   // (32,)
    float* __restrict__ out,
    int n_atoms)
{
    __shared__ float sA[64][33];
    __shared__ float sB[32][65];

    const int tx = threadIdx.x & 15;
    const int ty = threadIdx.x >> 4;
    const int r0 = blockIdx.x * 64;
    const int c0 = blockIdx.y * 64;

    for (int idx = threadIdx.x; idx < 64 * 32; idx += 256) {
        int r = idx >> 5, c = idx & 31;
        int gr = r0 + r;
        sA[r][c] = (gr < n_atoms) ? feat[gr * NF + c] : 0.0f;
    }
    for (int idx = threadIdx.x; idx < 32 * 64; idx += 256) {
        int k = idx >> 6, c = idx & 63;
        int gc = c0 + c;
        float v = 0.0f;
        if (gc < FWCOLS) {
            int o = gc >> 4, d = gc & 15;              // col = o*16 + d
            v = intw[d * (NF * NF) + o * NF + k];
        } else if (gc < BIGN) {
            v = selfw[(gc - FWCOLS) * NF + k];
        }
        sB[k][c] = v;
    }
    __syncthreads();

    float acc[4][4];
#pragma unroll
    for (int i = 0; i < 4; i++)
#pragma unroll
        for (int j = 0; j < 4; j++) acc[i][j] = 0.0f;

#pragma unroll
    for (int k = 0; k < 32; k++) {
        float a[4], b[4];
#pragma unroll
        for (int i = 0; i < 4; i++) a[i] = sA[ty + 16 * i][k];
#pragma unroll
        for (int j = 0; j < 4; j++) b[j] = sB[k][tx + 16 * j];
#pragma unroll
        for (int i = 0; i < 4; i++)
#pragma unroll
            for (int j = 0; j < 4; j++) acc[i][j] += a[i] * b[j];
    }

#pragma unroll
    for (int i = 0; i < 4; i++) {
        int gr = r0 + ty + 16 * i;
        if (gr >= n_atoms) continue;
#pragma unroll
        for (int j = 0; j < 4; j++) {
            int gc = c0 + tx + 16 * j;
            if (gc < FWCOLS) {
                d_fw[gr * FWCOLS + gc] = acc[i][j];
            } else if (gc < BIGN) {
                int o = gc - FWCOLS;
                out[gr * NF + o] = acc[i][j] + selfb[o];
            }
        }
    }
}

// ---------------------------------------------------------------------------
// K2: pair-sum + invariants + GroupNorm + mixing. One warp per atom.
// ---------------------------------------------------------------------------
#define K2_WARPS 8

__device__ __forceinline__ float warpsum(float v) {
#pragma unroll
    for (int o = 16; o > 0; o >>= 1) v += __shfl_xor_sync(0xffffffffu, v, o);
    return v;
}

__global__ __launch_bounds__(K2_WARPS * 32) void k2_atom(
    const float* __restrict__ rhats,   // (P,4)
    const int*   __restrict__ ps,      // (P,)
    const float* __restrict__ mixw,    // flat (64,32)
    const float* __restrict__ gnw,     // (64,)
    const float* __restrict__ gnb,     // (64,)
    float* __restrict__ out,           // (N,32), holds self_part
    int n_atoms)
{
    __shared__ float sh_mix[64 * 32];
    __shared__ float sh_norm[K2_WARPS][64];

    for (int i = threadIdx.x; i < 64 * 32; i += K2_WARPS * 32)
        sh_mix[i] = mixw[i];
    __syncthreads();

    const int warp = threadIdx.x >> 5;
    const int lane = threadIdx.x & 31;
    const int a = blockIdx.x * K2_WARPS + warp;
    if (a >= n_atoms) return;

    const int p0 = d_start[a];
    const int p1 = d_start[a + 1];

    float acc0 = 0.0f, acc1 = 0.0f, acc2 = 0.0f, acc3 = 0.0f;

#pragma unroll 4
    for (int p = p0; p < p1; p++) {
        const int j = ps[p];
        const float4* sp = reinterpret_cast<const float4*>(d_sens + (size_t)p * NDIST);
        const float4* fp = reinterpret_cast<const float4*>(d_fw + (size_t)j * FWCOLS + lane * NDIST);
        float4 s0 = sp[0], s1 = sp[1], s2 = sp[2], s3 = sp[3];
        float4 f0 = fp[0], f1 = fp[1], f2 = fp[2], f3 = fp[3];
        float m = s0.x * f0.x + s0.y * f0.y + s0.z * f0.z + s0.w * f0.w;
        m += s1.x * f1.x + s1.y * f1.y + s1.z * f1.z + s1.w * f1.w;
        m += s2.x * f2.x + s2.y * f2.y + s2.z * f2.z + s2.w * f2.w;
        m += s3.x * f3.x + s3.y * f3.y + s3.z * f3.z + s3.w * f3.w;
        float4 rh = *reinterpret_cast<const float4*>(rhats + (size_t)p * 4);
        acc0 += rh.x * m;
        acc1 += rh.y * m;
        acc2 += rh.z * m;
        acc3 += rh.w * m;
    }

    float inv0 = acc0;
    float inv1 = acc1 * acc1 + acc2 * acc2 + acc3 * acc3;

    float mean0 = warpsum(inv0) * (1.0f / 32.0f);
    float c0 = inv0 - mean0;
    float var0 = warpsum(c0 * c0) * (1.0f / 32.0f);
    float y0 = c0 * rsqrtf(var0 + GN_EPS) * gnw[lane] + gnb[lane];

    float mean1 = warpsum(inv1) * (1.0f / 32.0f);
    float c1 = inv1 - mean1;
    float var1 = warpsum(c1 * c1) * (1.0f / 32.0f);
    float y1 = c1 * rsqrtf(var1 + GN_EPS) * gnw[32 + lane] + gnb[32 + lane];

    sh_norm[warp][lane * 2 + 0] = y0;
    sh_norm[warp][lane * 2 + 1] = y1;
    __syncwarp();

    float o = 0.0f;
#pragma unroll
    for (int k = 0; k < 64; k++)
        o += sh_norm[warp][k] * sh_mix[k * 32 + lane];

    out[a * NF + lane] += o;
}

extern "C" void kernel_launch(void* const* d_in, const int* in_sizes, int n_in,
                              void* d_out, int out_size)
{
    const float* feat  = (const float*)d_in[0];
    const float* rhats = (const float*)d_in[1];
    const float* dist  = (const float*)d_in[2];
    const float* intw  = (const float*)d_in[3];
    const float* selfw = (const float*)d_in[4];
    const float* selfb = (const float*)d_in[5];
    const float* mixw  = (const float*)d_in[6];
    const float* gnw   = (const float*)d_in[7];
    const float* gnb   = (const float*)d_in[8];
    const float* mu    = (const float*)d_in[9];
    const float* sg    = (const float*)d_in[10];
    const int*   pf    = (const int*)d_in[11];
    const int*   ps    = (const int*)d_in[12];
    float* out = (float*)d_out;

    const int n_atoms = in_sizes[0] / NF;
    const int n_pairs = in_sizes[2];

    int k0_threads = n_pairs * NDIST;
    k0_prep<<<(k0_threads + 255) / 256, 256>>>(dist, mu, sg, pf, n_pairs, n_atoms);

    dim3 g1((n_atoms + 63) / 64, (BIGN + 63) / 64);
    k1_gemm<<<g1, 256>>>(feat, intw, selfw, selfb, out, n_atoms);

    int blocks = (n_atoms + K2_WARPS - 1) / K2_WARPS;
    k2_atom<<<blocks, K2_WARPS * 32>>>(rhats, ps, mixw, gnw, gnb, out, n_atoms);
}

// round 10
// speedup vs baseline: 1.1489x; 1.1489x over previous
#include <cuda_runtime.h>
#include <cuda_bf16.h>

#define MAX_ATOMS 8000
#define MAX_PAIRS 80000
#define NF 32
#define NDIST 16
#define FWCOLS (NDIST * NF)       // 512
#define BIGN (FWCOLS + NF)        // 544
#define GN_EPS 1e-5f
#define HARD_CUTOFF 6.5f
#define CUT_K 0.24166097335306083f   // 0.5*pi/6.5

// Scratch. fw layout: fw[j][d][o]  (d-major, o contiguous -> coalesced lane=o)
__device__ float d_fw[MAX_ATOMS * FWCOLS];
__device__ float d_sens[MAX_PAIRS * NDIST];
__device__ int   d_start[MAX_ATOMS + 1];

// ---------------------------------------------------------------------------
// K0: one thread per pair -> 16 sensitivities (float4 stores) + d_start table
// ---------------------------------------------------------------------------
__global__ __launch_bounds__(256) void k0_prep(
    const float* __restrict__ dist,
    const float* __restrict__ mu,
    const float* __restrict__ sigma,
    const int*   __restrict__ pf,
    int n_pairs, int n_atoms)
{
    __shared__ float smu[NDIST], sisig[NDIST];
    if (threadIdx.x < NDIST) {
        smu[threadIdx.x] = mu[threadIdx.x];
        sisig[threadIdx.x] = __fdividef(1.0f, sigma[threadIdx.x]);
    }
    __syncthreads();

    int p = blockIdx.x * blockDim.x + threadIdx.x;
    if (p >= n_pairs) return;

    float dv = dist[p];
    float invd = __fdividef(1.0f, dv);
    float cut = 0.0f;
    if (dv < HARD_CUTOFF) {
        float cc = __cosf(CUT_K * dv);
        cut = cc * cc;
    }
    float4* sdst = reinterpret_cast<float4*>(d_sens + (size_t)p * NDIST);
#pragma unroll
    for (int g = 0; g < 4; g++) {
        float s[4];
#pragma unroll
        for (int k = 0; k < 4; k++) {
            int dd = g * 4 + k;
            float t = (invd - smu[dd]) * sisig[dd];
            s[k] = __expf(-0.5f * t * t) * cut;
        }
        sdst[g] = make_float4(s[0], s[1], s[2], s[3]);
    }

    // segment-start table (pf sorted ascending)
    int a = pf[p];
    int prev = (p == 0) ? -1 : pf[p - 1];
    for (int x = prev + 1; x <= a; x++) d_start[x] = p;
    if (p == n_pairs - 1) {
        for (int x = a + 1; x <= n_atoms; x++) d_start[x] = n_pairs;
    }
}

// ---------------------------------------------------------------------------
// K1: fused GEMM  C(N x 544) = feat(N x 32) @ Wbig(32 x 544)
//   cols [0,512): fw with layout col = d*32 + o   (d-major, coalesced in K2)
//   cols [512,544): self_part -> d_out (+bias)
// ---------------------------------------------------------------------------
__global__ __launch_bounds__(256) void k1_gemm(
    const float* __restrict__ feat,
    const float* __restrict__ intw,    // (16,32,32)
    const float* __restrict__ selfw,   // (32,32)
    const float* __restrict__ selfb,   // (32,)
    float* __restrict__ out,
    int n_atoms)
{
    __shared__ float sA[64][33];
    __shared__ float sB[32][65];

    const int tx = threadIdx.x & 15;
    const int ty = threadIdx.x >> 4;
    const int r0 = blockIdx.x * 64;
    const int c0 = blockIdx.y * 64;

    for (int idx = threadIdx.x; idx < 64 * 32; idx += 256) {
        int r = idx >> 5, c = idx & 31;
        int gr = r0 + r;
        sA[r][c] = (gr < n_atoms) ? feat[gr * NF + c] : 0.0f;
    }
    for (int idx = threadIdx.x; idx < 32 * 64; idx += 256) {
        int k = idx >> 6, c = idx & 63;
        int gc = c0 + c;
        float v = 0.0f;
        if (gc < FWCOLS) {
            int d = gc >> 5, o = gc & 31;              // col = d*32 + o
            v = intw[d * (NF * NF) + o * NF + k];
        } else if (gc < BIGN) {
            v = selfw[(gc - FWCOLS) * NF + k];
        }
        sB[k][c] = v;
    }
    __syncthreads();

    float acc[4][4];
#pragma unroll
    for (int i = 0; i < 4; i++)
#pragma unroll
        for (int j = 0; j < 4; j++) acc[i][j] = 0.0f;

#pragma unroll
    for (int k = 0; k < 32; k++) {
        float a[4], b[4];
#pragma unroll
        for (int i = 0; i < 4; i++) a[i] = sA[ty + 16 * i][k];
#pragma unroll
        for (int j = 0; j < 4; j++) b[j] = sB[k][tx + 16 * j];
#pragma unroll
        for (int i = 0; i < 4; i++)
#pragma unroll
            for (int j = 0; j < 4; j++) acc[i][j] += a[i] * b[j];
    }

#pragma unroll
    for (int i = 0; i < 4; i++) {
        int gr = r0 + ty + 16 * i;
        if (gr >= n_atoms) continue;
#pragma unroll
        for (int j = 0; j < 4; j++) {
            int gc = c0 + tx + 16 * j;
            if (gc < FWCOLS) {
                d_fw[gr * FWCOLS + gc] = acc[i][j];
            } else if (gc < BIGN) {
                int o = gc - FWCOLS;
                out[gr * NF + o] = acc[i][j] + selfb[o];
            }
        }
    }
}

// ---------------------------------------------------------------------------
// K2: pair-sum + invariants + GroupNorm + mixing. One warp per atom.
// lane = output channel; fw loads are fully coalesced (1 line per LDG).
// ---------------------------------------------------------------------------
#define K2_WARPS 8

__device__ __forceinline__ float warpsum(float v) {
#pragma unroll
    for (int o = 16; o > 0; o >>= 1) v += __shfl_xor_sync(0xffffffffu, v, o);
    return v;
}

__global__ __launch_bounds__(K2_WARPS * 32) void k2_atom(
    const float* __restrict__ rhats,   // (P,4)
    const int*   __restrict__ ps,      // (P,)
    const float* __restrict__ mixw,    // flat (64,32)
    const float* __restrict__ gnw,     // (64,)
    const float* __restrict__ gnb,     // (64,)
    float* __restrict__ out,           // (N,32), holds self_part
    int n_atoms)
{
    __shared__ float sh_mix[64 * 32];
    __shared__ float sh_norm[K2_WARPS][64];

    for (int i = threadIdx.x; i < 64 * 32; i += K2_WARPS * 32)
        sh_mix[i] = mixw[i];
    __syncthreads();

    const int warp = threadIdx.x >> 5;
    const int lane = threadIdx.x & 31;
    const int a = blockIdx.x * K2_WARPS + warp;
    if (a >= n_atoms) return;

    const int p0 = d_start[a];
    const int p1 = d_start[a + 1];

    float acc0 = 0.0f, acc1 = 0.0f, acc2 = 0.0f, acc3 = 0.0f;

    for (int p = p0; p < p1; p++) {
        const int j = ps[p];
        // sensitivities: broadcast float4 loads (all lanes same address)
        const float4* sp = reinterpret_cast<const float4*>(d_sens + (size_t)p * NDIST);
        float4 s0 = sp[0], s1 = sp[1], s2 = sp[2], s3 = sp[3];
        // fw row: 16 coalesced scalar loads (lane = o, stride 32 floats per d)
        const float* fwj = d_fw + (size_t)j * FWCOLS + lane;
        float m;
        m  = s0.x * fwj[0 * 32] + s0.y * fwj[1 * 32] + s0.z * fwj[2 * 32] + s0.w * fwj[3 * 32];
        m += s1.x * fwj[4 * 32] + s1.y * fwj[5 * 32] + s1.z * fwj[6 * 32] + s1.w * fwj[7 * 32];
        m += s2.x * fwj[8 * 32] + s2.y * fwj[9 * 32] + s2.z * fwj[10 * 32] + s2.w * fwj[11 * 32];
        m += s3.x * fwj[12 * 32] + s3.y * fwj[13 * 32] + s3.z * fwj[14 * 32] + s3.w * fwj[15 * 32];
        float4 rh = *reinterpret_cast<const float4*>(rhats + (size_t)p * 4);
        acc0 += rh.x * m;
        acc1 += rh.y * m;
        acc2 += rh.z * m;
        acc3 += rh.w * m;
    }

    float inv0 = acc0;
    float inv1 = acc1 * acc1 + acc2 * acc2 + acc3 * acc3;

    float mean0 = warpsum(inv0) * (1.0f / 32.0f);
    float c0 = inv0 - mean0;
    float var0 = warpsum(c0 * c0) * (1.0f / 32.0f);
    float y0 = c0 * rsqrtf(var0 + GN_EPS) * gnw[lane] + gnb[lane];

    float mean1 = warpsum(inv1) * (1.0f / 32.0f);
    float c1 = inv1 - mean1;
    float var1 = warpsum(c1 * c1) * (1.0f / 32.0f);
    float y1 = c1 * rsqrtf(var1 + GN_EPS) * gnw[32 + lane] + gnb[32 + lane];

    sh_norm[warp][lane * 2 + 0] = y0;
    sh_norm[warp][lane * 2 + 1] = y1;
    __syncwarp();

    float o = 0.0f;
#pragma unroll
    for (int k = 0; k < 64; k++)
        o += sh_norm[warp][k] * sh_mix[k * 32 + lane];

    out[a * NF + lane] += o;
}

extern "C" void kernel_launch(void* const* d_in, const int* in_sizes, int n_in,
                              void* d_out, int out_size)
{
    const float* feat  = (const float*)d_in[0];
    const float* rhats = (const float*)d_in[1];
    const float* dist  = (const float*)d_in[2];
    const float* intw  = (const float*)d_in[3];
    const float* selfw = (const float*)d_in[4];
    const float* selfb = (const float*)d_in[5];
    const float* mixw  = (const float*)d_in[6];
    const float* gnw   = (const float*)d_in[7];
    const float* gnb   = (const float*)d_in[8];
    const float* mu    = (const float*)d_in[9];
    const float* sg    = (const float*)d_in[10];
    const int*   pf    = (const int*)d_in[11];
    const int*   ps    = (const int*)d_in[12];
    float* out = (float*)d_out;

    const int n_atoms = in_sizes[0] / NF;
    const int n_pairs = in_sizes[2];

    k0_prep<<<(n_pairs + 255) / 256, 256>>>(dist, mu, sg, pf, n_pairs, n_atoms);

    dim3 g1((n_atoms + 63) / 64, (BIGN + 63) / 64);
    k1_gemm<<<g1, 256>>>(feat, intw, selfw, selfb, out, n_atoms);

    int blocks = (n_atoms + K2_WARPS - 1) / K2_WARPS;
    k2_atom<<<blocks, K2_WARPS * 32>>>(rhats, ps, mixw, gnw, gnb, out, n_atoms);
}

// round 11
// speedup vs baseline: 1.3335x; 1.1607x over previous
#include <cuda_runtime.h>
#include <cuda_bf16.h>

#define MAX_ATOMS 8000
#define MAX_PAIRS 80000
#define NF 32
#define NDIST 16
#define FWCOLS (NDIST * NF)       // 512
#define BIGN (FWCOLS + NF)        // 544
#define GN_EPS 1e-5f
#define HARD_CUTOFF 6.5f
#define CUT_K 0.24166097335306083f   // 0.5*pi/6.5

// Scratch. fw layout: fw[j][d][o]  (d-major, o contiguous -> coalesced lane=o)
__device__ float d_fw[MAX_ATOMS * FWCOLS];
__device__ float d_sens[MAX_PAIRS * NDIST];
__device__ int   d_start[MAX_ATOMS + 1];

// ---------------------------------------------------------------------------
// KA: fused kernel. Blocks [0, gemm_blocks) run the GEMM
//     C(N x 544) = feat(N x 32) @ Wbig(32 x 544)  (cols 0-511 -> d_fw,
//     cols 512-543 -> self_part into d_out). Blocks [gemm_blocks, ...) run
//     the pair prep (sensitivities + d_start table). The two paths are
//     data-independent, so the ~7us first-kernel overhead of prep hides
//     under the GEMM.
// ---------------------------------------------------------------------------
__global__ __launch_bounds__(256) void ka_fused(
    const float* __restrict__ feat,
    const float* __restrict__ intw,    // (16,32,32)
    const float* __restrict__ selfw,   // (32,32)
    const float* __restrict__ selfb,   // (32,)
    const float* __restrict__ dist,    // (P,)
    const float* __restrict__ mu,      // (16,)
    const float* __restrict__ sigma,   // (16,)
    const int*   __restrict__ pf,      // (P,) sorted
    float* __restrict__ out,
    int n_atoms, int n_pairs, int gemm_bx, int gemm_blocks)
{
    __shared__ float sA[64][33];
    __shared__ float sB[32][65];
    __shared__ float smu[NDIST], sisig[NDIST];

    const int bid = blockIdx.x;

    if (bid < gemm_blocks) {
        // ---------------- GEMM path ----------------
        const int bx = bid % gemm_bx;
        const int by = bid / gemm_bx;
        const int tx = threadIdx.x & 15;
        const int ty = threadIdx.x >> 4;
        const int r0 = bx * 64;
        const int c0 = by * 64;

        for (int idx = threadIdx.x; idx < 64 * 32; idx += 256) {
            int r = idx >> 5, c = idx & 31;
            int gr = r0 + r;
            sA[r][c] = (gr < n_atoms) ? feat[gr * NF + c] : 0.0f;
        }
        for (int idx = threadIdx.x; idx < 32 * 64; idx += 256) {
            int k = idx >> 6, c = idx & 63;
            int gc = c0 + c;
            float v = 0.0f;
            if (gc < FWCOLS) {
                int d = gc >> 5, o = gc & 31;          // col = d*32 + o
                v = intw[d * (NF * NF) + o * NF + k];
            } else if (gc < BIGN) {
                v = selfw[(gc - FWCOLS) * NF + k];
            }
            sB[k][c] = v;
        }
        __syncthreads();

        float acc[4][4];
#pragma unroll
        for (int i = 0; i < 4; i++)
#pragma unroll
            for (int j = 0; j < 4; j++) acc[i][j] = 0.0f;

#pragma unroll
        for (int k = 0; k < 32; k++) {
            float a[4], b[4];
#pragma unroll
            for (int i = 0; i < 4; i++) a[i] = sA[ty + 16 * i][k];
#pragma unroll
            for (int j = 0; j < 4; j++) b[j] = sB[k][tx + 16 * j];
#pragma unroll
            for (int i = 0; i < 4; i++)
#pragma unroll
                for (int j = 0; j < 4; j++) acc[i][j] += a[i] * b[j];
        }

#pragma unroll
        for (int i = 0; i < 4; i++) {
            int gr = r0 + ty + 16 * i;
            if (gr >= n_atoms) continue;
#pragma unroll
            for (int j = 0; j < 4; j++) {
                int gc = c0 + tx + 16 * j;
                if (gc < FWCOLS) {
                    d_fw[gr * FWCOLS + gc] = acc[i][j];
                } else if (gc < BIGN) {
                    int o = gc - FWCOLS;
                    out[gr * NF + o] = acc[i][j] + selfb[o];
                }
            }
        }
    } else {
        // ---------------- prep path ----------------
        if (threadIdx.x < NDIST) {
            smu[threadIdx.x] = mu[threadIdx.x];
            sisig[threadIdx.x] = __fdividef(1.0f, sigma[threadIdx.x]);
        }
        __syncthreads();

        int p = (bid - gemm_blocks) * 256 + threadIdx.x;
        if (p >= n_pairs) return;

        float dv = dist[p];
        float invd = __fdividef(1.0f, dv);
        float cut = 0.0f;
        if (dv < HARD_CUTOFF) {
            float cc = __cosf(CUT_K * dv);
            cut = cc * cc;
        }
        float4* sdst = reinterpret_cast<float4*>(d_sens + (size_t)p * NDIST);
#pragma unroll
        for (int g = 0; g < 4; g++) {
            float s[4];
#pragma unroll
            for (int k = 0; k < 4; k++) {
                int dd = g * 4 + k;
                float t = (invd - smu[dd]) * sisig[dd];
                s[k] = __expf(-0.5f * t * t) * cut;
            }
            sdst[g] = make_float4(s[0], s[1], s[2], s[3]);
        }

        // segment-start table (pf sorted ascending)
        int a = pf[p];
        int prev = (p == 0) ? -1 : pf[p - 1];
        for (int x = prev + 1; x <= a; x++) d_start[x] = p;
        if (p == n_pairs - 1) {
            for (int x = a + 1; x <= n_atoms; x++) d_start[x] = n_pairs;
        }
    }
}

// ---------------------------------------------------------------------------
// K2: pair-sum + invariants + GroupNorm + mixing.
// TWO warps per atom (interleaved pair split) -> 2x warps, half the serial
// dependent-load chain per warp. Odd warp dumps partial accs to shared;
// even warp combines and runs the epilogue.
// ---------------------------------------------------------------------------
#define K2_APB 4   // atoms per block (8 warps / 2)

__device__ __forceinline__ float warpsum(float v) {
#pragma unroll
    for (int o = 16; o > 0; o >>= 1) v += __shfl_xor_sync(0xffffffffu, v, o);
    return v;
}

__global__ __launch_bounds__(256) void k2_atom(
    const float* __restrict__ rhats,   // (P,4)
    const int*   __restrict__ ps,      // (P,)
    const float* __restrict__ mixw,    // flat (64,32)
    const float* __restrict__ gnw,     // (64,)
    const float* __restrict__ gnb,     // (64,)
    float* __restrict__ out,           // (N,32), holds self_part
    int n_atoms)
{
    __shared__ float sh_mix[64 * 32];
    __shared__ float sh_acc[K2_APB][4][32];
    __shared__ float sh_norm[K2_APB][64];

    for (int i = threadIdx.x; i < 64 * 32; i += 256)
        sh_mix[i] = mixw[i];

    const int warp = threadIdx.x >> 5;
    const int lane = threadIdx.x & 31;
    const int al   = warp >> 1;        // atom slot in block
    const int half = warp & 1;         // which half of the pair list
    const int a = blockIdx.x * K2_APB + al;

    float acc0 = 0.0f, acc1 = 0.0f, acc2 = 0.0f, acc3 = 0.0f;

    if (a < n_atoms) {
        const int p0 = d_start[a];
        const int p1 = d_start[a + 1];

        for (int p = p0 + half; p < p1; p += 2) {
            const int j = ps[p];
            // sensitivities: broadcast float4 loads (all lanes same address)
            const float4* sp = reinterpret_cast<const float4*>(d_sens + (size_t)p * NDIST);
            float4 s0 = sp[0], s1 = sp[1], s2 = sp[2], s3 = sp[3];
            // fw row: 16 coalesced scalar loads (lane = o, stride 32 floats per d)
            const float* fwj = d_fw + (size_t)j * FWCOLS + lane;
            float m;
            m  = s0.x * fwj[0 * 32] + s0.y * fwj[1 * 32] + s0.z * fwj[2 * 32] + s0.w * fwj[3 * 32];
            m += s1.x * fwj[4 * 32] + s1.y * fwj[5 * 32] + s1.z * fwj[6 * 32] + s1.w * fwj[7 * 32];
            m += s2.x * fwj[8 * 32] + s2.y * fwj[9 * 32] + s2.z * fwj[10 * 32] + s2.w * fwj[11 * 32];
            m += s3.x * fwj[12 * 32] + s3.y * fwj[13 * 32] + s3.z * fwj[14 * 32] + s3.w * fwj[15 * 32];
            float4 rh = *reinterpret_cast<const float4*>(rhats + (size_t)p * 4);
            acc0 += rh.x * m;
            acc1 += rh.y * m;
            acc2 += rh.z * m;
            acc3 += rh.w * m;
        }
    }

    if (half == 1) {
        sh_acc[al][0][lane] = acc0;
        sh_acc[al][1][lane] = acc1;
        sh_acc[al][2][lane] = acc2;
        sh_acc[al][3][lane] = acc3;
    }
    __syncthreads();   // orders sh_acc AND sh_mix before use

    if (half == 1 || a >= n_atoms) return;

    acc0 += sh_acc[al][0][lane];
    acc1 += sh_acc[al][1][lane];
    acc2 += sh_acc[al][2][lane];
    acc3 += sh_acc[al][3][lane];

    float inv0 = acc0;
    float inv1 = acc1 * acc1 + acc2 * acc2 + acc3 * acc3;

    float mean0 = warpsum(inv0) * (1.0f / 32.0f);
    float c0 = inv0 - mean0;
    float var0 = warpsum(c0 * c0) * (1.0f / 32.0f);
    float y0 = c0 * rsqrtf(var0 + GN_EPS) * gnw[lane] + gnb[lane];

    float mean1 = warpsum(inv1) * (1.0f / 32.0f);
    float c1 = inv1 - mean1;
    float var1 = warpsum(c1 * c1) * (1.0f / 32.0f);
    float y1 = c1 * rsqrtf(var1 + GN_EPS) * gnw[32 + lane] + gnb[32 + lane];

    sh_norm[al][lane * 2 + 0] = y0;
    sh_norm[al][lane * 2 + 1] = y1;
    __syncwarp();

    float o = 0.0f;
#pragma unroll
    for (int k = 0; k < 64; k++)
        o += sh_norm[al][k] * sh_mix[k * 32 + lane];

    out[a * NF + lane] += o;
}

extern "C" void kernel_launch(void* const* d_in, const int* in_sizes, int n_in,
                              void* d_out, int out_size)
{
    const float* feat  = (const float*)d_in[0];
    const float* rhats = (const float*)d_in[1];
    const float* dist  = (const float*)d_in[2];
    const float* intw  = (const float*)d_in[3];
    const float* selfw = (const float*)d_in[4];
    const float* selfb = (const float*)d_in[5];
    const float* mixw  = (const float*)d_in[6];
    const float* gnw   = (const float*)d_in[7];
    const float* gnb   = (const float*)d_in[8];
    const float* mu    = (const float*)d_in[9];
    const float* sg    = (const float*)d_in[10];
    const int*   pf    = (const int*)d_in[11];
    const int*   ps    = (const int*)d_in[12];
    float* out = (float*)d_out;

    const int n_atoms = in_sizes[0] / NF;
    const int n_pairs = in_sizes[2];

    const int gemm_bx = (n_atoms + 63) / 64;
    const int gemm_blocks = gemm_bx * ((BIGN + 63) / 64);
    const int prep_blocks = (n_pairs + 255) / 256;

    ka_fused<<<gemm_blocks + prep_blocks, 256>>>(
        feat, intw, selfw, selfb, dist, mu, sg, pf,
        out, n_atoms, n_pairs, gemm_bx, gemm_blocks);

    int blocks = (n_atoms + K2_APB - 1) / K2_APB;
    k2_atom<<<blocks, 256>>>(rhats, ps, mixw, gnw, gnb, out, n_atoms);
}